// round 3
// baseline (speedup 1.0000x reference)
#include <cuda_runtime.h>

// Locally-connected 3x3 conv, unshared weights:
// out[b,i,j] = 9 * sum_{m,n} x[b,i+m,j+n] * w[i,j,3m+n] + sum_k b[i,j,k]
// x zero-padded on the high side of both spatial dims.
//
// Block = 256 threads = jt(16 col-pairs) x ii(4 rows) x bq(4).
// Grid  = (8 col-tiles, 64 row-tiles, 4 batch-subgroups) = 2048 blocks.
// Each thread computes 2 cols x 4 batches (fully unrolled, MLP ~24).

#define Wd 256
#define Hd 256
#define Bn 64
#define IMG ((size_t)Wd * Hd)

__global__ __launch_bounds__(256, 5)
void lc_kernel(const float* __restrict__ x,
               const float* __restrict__ w,
               const float* __restrict__ bvec,
               float* __restrict__ out) {
    __shared__ float ws[1152];   // 4 rows x 32 cols x 9
    __shared__ float bs[1152];

    const int t  = threadIdx.x;
    const int jt = t & 15;          // 0..15 : column pair
    const int ii = (t >> 4) & 3;    // 0..3  : row within tile
    const int bq = t >> 6;          // 0..3  : batch quarter

    const int i0 = blockIdx.y * 4;
    const int j0 = blockIdx.x * 32;
    const int i  = i0 + ii;
    const int j  = j0 + jt * 2;

    // ---- stage w/b tile into smem (coalesced), once per block ----
    #pragma unroll
    for (int idx = t; idx < 1152; idx += 256) {
        int r    = idx / 288;            // row within tile
        int rest = idx - r * 288;        // 32 cols * 9 units
        size_t g = ((size_t)(i0 + r) * Hd + j0) * 9 + rest;
        ws[idx] = w[g];
        bs[idx] = bvec[g];
    }
    __syncthreads();

    // ---- per-thread weights (2 cols x 9) and bias sums -> registers ----
    float wr[2][9];
    float bsum[2];
    #pragma unroll
    for (int c = 0; c < 2; c++) {
        const float* pw = &ws[(ii * 32 + jt * 2 + c) * 9];
        const float* pb = &bs[(ii * 32 + jt * 2 + c) * 9];
        float s = 0.f;
        #pragma unroll
        for (int k = 0; k < 9; k++) { wr[c][k] = pw[k]; s += pb[k]; }
        bsum[c] = s;
    }

    const bool qok  = (j + 2 < Hd);     // cols j+2, j+3 exist
    const bool r1ok = (i + 1 < Wd);
    const bool r2ok = (i + 2 < Wd);
    const float2 z2 = make_float2(0.f, 0.f);

    const int b0 = bq * 16 + blockIdx.z * 4;      // first of 4 batches
    size_t xoff  = (size_t)b0 * IMG + (size_t)i * Hd + j;

    #pragma unroll
    for (int bi = 0; bi < 4; bi++) {
        const float* xb = x + xoff + (size_t)bi * IMG;

        float2 p0, q0, p1, q1, p2, q2;
        p0 = *(const float2*)xb;
        q0 = qok ? *(const float2*)(xb + 2) : z2;
        if (r1ok) {
            p1 = *(const float2*)(xb + Hd);
            q1 = qok ? *(const float2*)(xb + Hd + 2) : z2;
        } else { p1 = z2; q1 = z2; }
        if (r2ok) {
            p2 = *(const float2*)(xb + 2 * Hd);
            q2 = qok ? *(const float2*)(xb + 2 * Hd + 2) : z2;
        } else { p2 = z2; q2 = z2; }

        float a0 = p0.x * wr[0][0];
        a0 = fmaf(p0.y, wr[0][1], a0);
        a0 = fmaf(q0.x, wr[0][2], a0);
        a0 = fmaf(p1.x, wr[0][3], a0);
        a0 = fmaf(p1.y, wr[0][4], a0);
        a0 = fmaf(q1.x, wr[0][5], a0);
        a0 = fmaf(p2.x, wr[0][6], a0);
        a0 = fmaf(p2.y, wr[0][7], a0);
        a0 = fmaf(q2.x, wr[0][8], a0);

        float a1 = p0.y * wr[1][0];
        a1 = fmaf(q0.x, wr[1][1], a1);
        a1 = fmaf(q0.y, wr[1][2], a1);
        a1 = fmaf(p1.y, wr[1][3], a1);
        a1 = fmaf(q1.x, wr[1][4], a1);
        a1 = fmaf(q1.y, wr[1][5], a1);
        a1 = fmaf(p2.y, wr[1][6], a1);
        a1 = fmaf(q2.x, wr[1][7], a1);
        a1 = fmaf(q2.y, wr[1][8], a1);

        *(float2*)(out + xoff + (size_t)bi * IMG) =
            make_float2(fmaf(9.f, a0, bsum[0]), fmaf(9.f, a1, bsum[1]));
    }
}

extern "C" void kernel_launch(void* const* d_in, const int* in_sizes, int n_in,
                              void* d_out, int out_size) {
    const float* x   = (const float*)d_in[0];
    const float* w   = (const float*)d_in[1];
    const float* b   = (const float*)d_in[2];
    float*       out = (float*)d_out;

    dim3 grid(8, 64, 4);   // (j-tiles of 32, i-tiles of 4, batch subgroups)
    lc_kernel<<<grid, 256>>>(x, w, b, out);
}

// round 4
// speedup vs baseline: 1.0408x; 1.0408x over previous
#include <cuda_runtime.h>

// Locally-connected 3x3 conv, unshared weights:
// out[b,i,j] = 9 * sum_{m,n} x[b,i+m,j+n] * w[i,j,3m+n] + sum_k b[i,j,k]
// x zero-padded on the high side of both spatial dims.
//
// Block = 256 threads = qt(16 col-quads = 64 cols) x ii(2 rows) x bq(8).
// Grid  = (4 col-tiles, 128 row-tiles) = 512 blocks.
// Each thread: 4 adjacent cols (float4 loads/stores) x 8 batches.
// Weights staged once per block (amplification 1x), register-resident.

#define Wd 256
#define Hd 256
#define IMG ((size_t)Wd * Hd)

__global__ __launch_bounds__(256, 3)
void lc_kernel(const float* __restrict__ x,
               const float* __restrict__ w,
               const float* __restrict__ bvec,
               float* __restrict__ out) {
    __shared__ float ws[1152];   // 2 rows x 64 cols x 9
    __shared__ float bs[1152];

    const int t  = threadIdx.x;
    const int qt = t & 15;          // 0..15 : column quad
    const int ii = (t >> 4) & 1;    // 0..1  : row within tile
    const int bq = t >> 5;          // 0..7  : batch eighth

    const int i0 = blockIdx.y * 2;
    const int j0 = blockIdx.x * 64;
    const int i  = i0 + ii;
    const int j  = j0 + qt * 4;

    // ---- stage w/b tile (coalesced), once per block ----
    #pragma unroll
    for (int idx = t; idx < 1152; idx += 256) {
        int r    = (idx >= 576);         // row within tile
        int rest = idx - r * 576;        // 64 cols * 9 units
        size_t g = ((size_t)(i0 + r) * Hd + j0) * 9 + rest;
        ws[idx] = w[g];
        bs[idx] = bvec[g];
    }
    __syncthreads();

    // ---- per-thread weights (4 cols x 9) + bias sums -> registers ----
    float wr[4][9];
    float bsum[4];
    {
        const int base = ii * 576 + qt * 36;
        #pragma unroll
        for (int c = 0; c < 4; c++) {
            float s = 0.f;
            #pragma unroll
            for (int k = 0; k < 9; k++) {
                wr[c][k] = ws[base + c * 9 + k];
                s += bs[base + c * 9 + k];
            }
            bsum[c] = s;
        }
    }

    const bool qok  = (j + 4 < Hd);     // second float4 in-bounds
    const bool r1ok = (i + 1 < Wd);
    const bool r2ok = (i + 2 < Wd);
    const float4 z4 = make_float4(0.f, 0.f, 0.f, 0.f);

    size_t off = (size_t)(bq * 8) * IMG + (size_t)i * Hd + j;

    for (int bi = 0; bi < 8; bi++) {
        const float* xb = x + off;

        float4 A0, B0, A1, B1, A2, B2;
        A0 = *(const float4*)xb;
        B0 = qok ? *(const float4*)(xb + 4) : z4;
        if (r1ok) {
            A1 = *(const float4*)(xb + Hd);
            B1 = qok ? *(const float4*)(xb + Hd + 4) : z4;
        } else { A1 = z4; B1 = z4; }
        if (r2ok) {
            A2 = *(const float4*)(xb + 2 * Hd);
            B2 = qok ? *(const float4*)(xb + 2 * Hd + 4) : z4;
        } else { A2 = z4; B2 = z4; }

        // windows as flat arrays (constant indices -> registers)
        const float r0[8] = {A0.x, A0.y, A0.z, A0.w, B0.x, B0.y, B0.z, B0.w};
        const float r1[8] = {A1.x, A1.y, A1.z, A1.w, B1.x, B1.y, B1.z, B1.w};
        const float r2[8] = {A2.x, A2.y, A2.z, A2.w, B2.x, B2.y, B2.z, B2.w};

        float acc[4];
        #pragma unroll
        for (int c = 0; c < 4; c++) {
            float a = r0[c] * wr[c][0];
            a = fmaf(r0[c + 1], wr[c][1], a);
            a = fmaf(r0[c + 2], wr[c][2], a);
            a = fmaf(r1[c],     wr[c][3], a);
            a = fmaf(r1[c + 1], wr[c][4], a);
            a = fmaf(r1[c + 2], wr[c][5], a);
            a = fmaf(r2[c],     wr[c][6], a);
            a = fmaf(r2[c + 1], wr[c][7], a);
            a = fmaf(r2[c + 2], wr[c][8], a);
            acc[c] = fmaf(9.f, a, bsum[c]);
        }

        *(float4*)(out + off) = make_float4(acc[0], acc[1], acc[2], acc[3]);

        off += IMG;
    }
}

extern "C" void kernel_launch(void* const* d_in, const int* in_sizes, int n_in,
                              void* d_out, int out_size) {
    const float* x   = (const float*)d_in[0];
    const float* w   = (const float*)d_in[1];
    const float* b   = (const float*)d_in[2];
    float*       out = (float*)d_out;

    dim3 grid(4, 128);   // (col-tiles of 64, row-tiles of 2)
    lc_kernel<<<grid, 256>>>(x, w, b, out);
}